// round 9
// baseline (speedup 1.0000x reference)
#include <cuda_runtime.h>
#include <cuda_fp16.h>
#include <math.h>

#define NN 50000
#define NE 800000
#define NET (NE + NN)
#define NG 256
#define NB ((NN + 255) / 256)

// ---------------- device scratch ------------------------------------------
__device__ __half   g_h1[NN * 64];
__device__ float    g_ssrc1[NN * 4];
__device__ float    g_sdst1[NN * 4];
__device__ float    g_out1[NN * 64];
__device__ __half   g_h2[NN * 256];
__device__ float    g_ssrc2[NN];
__device__ float    g_sdst2[NN];
__device__ float    g_out2[NN * 256];
__device__ int      g_counts[NN];     // zero-init at load; re-zeroed by offs_kernel
__device__ int      g_offsets[NN + 1];
__device__ int      g_bsums[NB];
__device__ int      g_epos[NET];
__device__ int      g_csr_src[NET];
__device__ float    g_poolf[NG * 256];
__device__ float    g_z1[NG * 512];
__device__ float    g_z2[NG * 1024];

// ---------------- helpers --------------------------------------------------
__device__ __forceinline__ float leaky(float x) { return x > 0.f ? x : 0.2f * x; }
__device__ __forceinline__ float elu(float x)   { return x > 0.f ? x : expm1f(x); }

// ---------------- prep -----------------------------------------------------
// histogram + intra-bucket position (scatter then needs no atomics)
__global__ void hist_kernel(const int* __restrict__ ei) {
    int e = blockIdx.x * blockDim.x + threadIdx.x;
    if (e >= NET) return;
    int dst = (e < NE) ? ei[NE + e] : (e - NE);
    g_epos[e] = atomicAdd(&g_counts[dst], 1);
}

__global__ void bsum_kernel() {
    __shared__ int ws[8];
    int i = blockIdx.x * 256 + threadIdx.x;
    int v = (i < NN) ? g_counts[i] : 0;
    #pragma unroll
    for (int off = 16; off; off >>= 1) v += __shfl_xor_sync(0xffffffffu, v, off);
    int lane = threadIdx.x & 31, wid = threadIdx.x >> 5;
    if (lane == 0) ws[wid] = v;
    __syncthreads();
    if (threadIdx.x == 0) {
        int s = 0;
        #pragma unroll
        for (int w = 0; w < 8; w++) s += ws[w];
        g_bsums[blockIdx.x] = s;
    }
}

__global__ void bscan_kernel() {
    __shared__ int wsum[8];
    int t = threadIdx.x, lane = t & 31, wid = t >> 5;
    int v = (t < NB) ? g_bsums[t] : 0;
    int s = v;
    #pragma unroll
    for (int off = 1; off < 32; off <<= 1) {
        int u = __shfl_up_sync(0xffffffffu, s, off);
        if (lane >= off) s += u;
    }
    if (lane == 31) wsum[wid] = s;
    __syncthreads();
    if (wid == 0 && lane < 8) {
        int ws = wsum[lane];
        #pragma unroll
        for (int off = 1; off < 8; off <<= 1) {
            int u = __shfl_up_sync(0xffu, ws, off);
            if (lane >= off) ws += u;
        }
        wsum[lane] = ws;
    }
    __syncthreads();
    int pre = (wid > 0) ? wsum[wid - 1] : 0;
    if (t < NB) g_bsums[t] = pre + s - v;
}

// offsets from counts + block bases; zeroes counts afterwards (so the next
// graph replay's hist_kernel starts from zero — same state as module load)
__global__ void offs_kernel() {
    __shared__ int wsum[8];
    int t = threadIdx.x, lane = t & 31, wid = t >> 5;
    int i = blockIdx.x * 256 + t;
    int v = (i < NN) ? g_counts[i] : 0;
    int s = v;
    #pragma unroll
    for (int off = 1; off < 32; off <<= 1) {
        int u = __shfl_up_sync(0xffffffffu, s, off);
        if (lane >= off) s += u;
    }
    if (lane == 31) wsum[wid] = s;
    __syncthreads();
    if (wid == 0 && lane < 8) {
        int ws = wsum[lane];
        #pragma unroll
        for (int off = 1; off < 8; off <<= 1) {
            int u = __shfl_up_sync(0xffu, ws, off);
            if (lane >= off) ws += u;
        }
        wsum[lane] = ws;
    }
    __syncthreads();
    int pre = (wid > 0) ? wsum[wid - 1] : 0;
    if (i < NN) {
        g_offsets[i] = g_bsums[blockIdx.x] + pre + s - v;
        g_counts[i] = 0;
    }
    if (i == 0) g_offsets[NN] = NET;
}

__global__ void scatter_kernel(const int* __restrict__ ei) {
    int e = blockIdx.x * blockDim.x + threadIdx.x;
    if (e >= NET) return;
    int src, dst;
    if (e < NE) { src = ei[e]; dst = ei[NE + e]; }
    else        { src = dst = e - NE; }
    g_csr_src[g_offsets[dst] + g_epos[e]] = src;
}

// ---------------- GAT layer 1 ----------------------------------------------
// h1 = x @ W1 (fp16 store), fused s1 (16-lane butterfly per head)
__global__ void gemm1_kernel(const float* __restrict__ x, const float* __restrict__ W1,
                             const float* __restrict__ a_src, const float* __restrict__ a_dst) {
    int idx = blockIdx.x * blockDim.x + threadIdx.x;   // NN*64 exact
    int n = idx >> 6, j = idx & 63;
    const float* xr = x + n * 27;
    float acc = 0.f;
    #pragma unroll
    for (int k = 0; k < 27; k++) acc += xr[k] * W1[k * 64 + j];
    g_h1[idx] = __float2half_rn(acc);
    float ps = acc * a_src[j];
    float pd = acc * a_dst[j];
    #pragma unroll
    for (int off = 8; off; off >>= 1) {
        ps += __shfl_xor_sync(0xffffffffu, ps, off);
        pd += __shfl_xor_sync(0xffffffffu, pd, off);
    }
    if ((j & 15) == 0) {
        int h = j >> 4;
        g_ssrc1[n * 4 + h] = ps;
        g_sdst1[n * 4 + h] = pd;
    }
}

// fused attention+aggregation, layer 1: warp per node.
// Sweep 1: online softmax stats (mx, den) per head, in registers.
// Sweep 2: batches of 32 edges; lane k loads edge k's (src, w4); warp then
// iterates the batch with shfl broadcasts while all 32 lanes load the 128B
// h1 row coalescedly (2 fp16 channels per lane).
__global__ void attnagg1_kernel(const float* __restrict__ b1) {
    int node = blockIdx.x * 8 + (threadIdx.x >> 5);
    if (node >= NN) return;
    int lane = threadIdx.x & 31;
    int beg = g_offsets[node], end = g_offsets[node + 1];
    float4 sd = *(const float4*)(g_sdst1 + node * 4);

    float mx[4], den[4];
    #pragma unroll
    for (int h = 0; h < 4; h++) { mx[h] = -3.4e38f; den[h] = 0.f; }
    for (int i = beg + lane; i < end; i += 32) {
        int s = g_csr_src[i];
        float4 sv = *(const float4*)(g_ssrc1 + s * 4);
        float v[4] = { leaky(sv.x + sd.x), leaky(sv.y + sd.y),
                       leaky(sv.z + sd.z), leaky(sv.w + sd.w) };
        #pragma unroll
        for (int h = 0; h < 4; h++) {
            float nm = fmaxf(mx[h], v[h]);
            den[h] = den[h] * __expf(mx[h] - nm) + __expf(v[h] - nm);
            mx[h] = nm;
        }
    }
    #pragma unroll
    for (int h = 0; h < 4; h++) {
        #pragma unroll
        for (int off = 16; off; off >>= 1) {
            float omx = __shfl_xor_sync(0xffffffffu, mx[h], off);
            float ode = __shfl_xor_sync(0xffffffffu, den[h], off);
            float nm = fmaxf(mx[h], omx);
            den[h] = den[h] * __expf(mx[h] - nm) + ode * __expf(omx - nm);
            mx[h] = nm;
        }
    }
    // lane holds channels 2*lane, 2*lane+1; head = lane >> 3
    int hL = lane >> 3;
    float myinv = 1.f / (((hL == 0) ? den[0] : (hL == 1) ? den[1]
                          : (hL == 2) ? den[2] : den[3]) + 1e-16f);

    float acc0 = 0.f, acc1 = 0.f;
    for (int base = beg; base < end; base += 32) {
        int i = base + lane;
        int s = 0;
        float4 w4 = make_float4(0.f, 0.f, 0.f, 0.f);
        if (i < end) {
            s = g_csr_src[i];
            float4 sv = *(const float4*)(g_ssrc1 + s * 4);
            w4.x = __expf(leaky(sv.x + sd.x) - mx[0]);
            w4.y = __expf(leaky(sv.y + sd.y) - mx[1]);
            w4.z = __expf(leaky(sv.z + sd.z) - mx[2]);
            w4.w = __expf(leaky(sv.w + sd.w) - mx[3]);
        }
        int cnt = min(32, end - base);
        for (int k = 0; k < cnt; k++) {
            int   ss = __shfl_sync(0xffffffffu, s, k);
            float wx = __shfl_sync(0xffffffffu, w4.x, k);
            float wy = __shfl_sync(0xffffffffu, w4.y, k);
            float wz = __shfl_sync(0xffffffffu, w4.z, k);
            float ww = __shfl_sync(0xffffffffu, w4.w, k);
            float w  = (hL == 0) ? wx : (hL == 1) ? wy : (hL == 2) ? wz : ww;
            __half2 hv = *(const __half2*)(g_h1 + ss * 64 + lane * 2);
            float2 f = __half22float2(hv);
            acc0 += w * f.x;
            acc1 += w * f.y;
        }
    }
    float2 bb = *(const float2*)(b1 + lane * 2);
    float2 o;
    o.x = elu(acc0 * myinv + bb.x);
    o.y = elu(acc1 * myinv + bb.y);
    *(float2*)(g_out1 + node * 64 + lane * 2) = o;
}

// ---------------- GAT layer 2 ----------------------------------------------
// h2 = out1 @ W2 -> fp16; s2 fused. 16 rows / 256-thread block.
__global__ void gemm2_kernel(const float* __restrict__ W2,
                             const float* __restrict__ a_src, const float* __restrict__ a_dst) {
    __shared__ float sA[16][64];
    __shared__ float sred[8][16][2];
    int nodeBase = blockIdx.x * 16;          // 3125 blocks, exact
    int tid = threadIdx.x;
    for (int t = tid; t < 16 * 64; t += 256) {
        int r = t >> 6, c = t & 63;
        sA[r][c] = g_out1[(nodeBase + r) * 64 + c];
    }
    __syncthreads();
    float acc[16];
    #pragma unroll
    for (int r = 0; r < 16; r++) acc[r] = 0.f;
    int j = tid;
    #pragma unroll 4
    for (int k = 0; k < 64; k++) {
        float w = W2[k * 256 + j];
        #pragma unroll
        for (int r = 0; r < 16; r++) acc[r] += sA[r][k] * w;
    }
    float aj_s = a_src[j], aj_d = a_dst[j];
    int lane = tid & 31, wid = tid >> 5;
    #pragma unroll
    for (int r = 0; r < 16; r++) {
        g_h2[(nodeBase + r) * 256 + j] = __float2half_rn(acc[r]);
        float ps = acc[r] * aj_s, pd = acc[r] * aj_d;
        #pragma unroll
        for (int off = 16; off; off >>= 1) {
            ps += __shfl_xor_sync(0xffffffffu, ps, off);
            pd += __shfl_xor_sync(0xffffffffu, pd, off);
        }
        if (lane == 0) { sred[wid][r][0] = ps; sred[wid][r][1] = pd; }
    }
    __syncthreads();
    if (tid < 32) {
        int r = tid >> 1, which = tid & 1;
        float s = 0.f;
        #pragma unroll
        for (int w = 0; w < 8; w++) s += sred[w][r][which];
        if (which == 0) g_ssrc2[nodeBase + r] = s;
        else            g_sdst2[nodeBase + r] = s;
    }
}

// fused attention+aggregation, layer 2 (H=1): warp per node, 8 ch/lane.
__global__ void attnagg2_kernel(const float* __restrict__ b2) {
    int node = blockIdx.x * 8 + (threadIdx.x >> 5);
    if (node >= NN) return;
    int lane = threadIdx.x & 31;
    int beg = g_offsets[node], end = g_offsets[node + 1];
    float sd = g_sdst2[node];

    float mx = -3.4e38f, den = 0.f;
    for (int i = beg + lane; i < end; i += 32) {
        int s = g_csr_src[i];
        float v = leaky(g_ssrc2[s] + sd);
        float nm = fmaxf(mx, v);
        den = den * __expf(mx - nm) + __expf(v - nm);
        mx = nm;
    }
    #pragma unroll
    for (int off = 16; off; off >>= 1) {
        float omx = __shfl_xor_sync(0xffffffffu, mx, off);
        float ode = __shfl_xor_sync(0xffffffffu, den, off);
        float nm = fmaxf(mx, omx);
        den = den * __expf(mx - nm) + ode * __expf(omx - nm);
        mx = nm;
    }
    float inv = 1.f / (den + 1e-16f);

    float acc[8];
    #pragma unroll
    for (int c = 0; c < 8; c++) acc[c] = 0.f;
    const __half* h2 = g_h2;
    for (int base = beg; base < end; base += 32) {
        int i = base + lane;
        int s = 0;
        float w = 0.f;
        if (i < end) {
            s = g_csr_src[i];
            w = __expf(leaky(g_ssrc2[s] + sd) - mx);
        }
        int cnt = min(32, end - base);
        for (int k = 0; k < cnt; k++) {
            int   ss = __shfl_sync(0xffffffffu, s, k);
            float wk = __shfl_sync(0xffffffffu, w, k);
            uint4 raw = *(const uint4*)(h2 + ss * 256 + lane * 8);
            const __half2* hp = (const __half2*)&raw;
            #pragma unroll
            for (int c = 0; c < 4; c++) {
                float2 v = __half22float2(hp[c]);
                acc[2 * c]     += wk * v.x;
                acc[2 * c + 1] += wk * v.y;
            }
        }
    }
    #pragma unroll
    for (int c = 0; c < 8; c++)
        g_out2[node * 256 + lane * 8 + c] = elu(acc[c] * inv + b2[lane * 8 + c]);
}

// ---------------- pool + MLP ------------------------------------------------
__global__ void pool_kernel() {
    int g = blockIdx.x;
    int j = threadIdx.x;
    int start = (g * NN + NG - 1) / NG;
    int end   = ((g + 1) * NN + NG - 1) / NG;
    float mx = -3.4e38f;
    for (int n = start; n < end; n++)
        mx = fmaxf(mx, g_out2[n * 256 + j]);
    g_poolf[g * 256 + j] = mx;
}

__global__ void mlp_tiled_kernel(const float* __restrict__ A, const float* __restrict__ W,
                                 const float* __restrict__ b, float* __restrict__ C,
                                 int K, int Nc, int do_relu) {
    __shared__ float sA[16][64];
    int rowBase = blockIdx.y * 16;
    int j = blockIdx.x * 256 + threadIdx.x;
    float acc[16];
    #pragma unroll
    for (int r = 0; r < 16; r++) acc[r] = 0.f;
    for (int k0 = 0; k0 < K; k0 += 64) {
        for (int t = threadIdx.x; t < 16 * 64; t += 256) {
            int r = t >> 6, c = t & 63;
            sA[r][c] = A[(rowBase + r) * K + k0 + c];
        }
        __syncthreads();
        #pragma unroll 4
        for (int kk = 0; kk < 64; kk++) {
            float w = W[(k0 + kk) * Nc + j];
            #pragma unroll
            for (int r = 0; r < 16; r++) acc[r] += sA[r][kk] * w;
        }
        __syncthreads();
    }
    float bj = b[j];
    #pragma unroll
    for (int r = 0; r < 16; r++) {
        float v = acc[r] + bj;
        if (do_relu) v = fmaxf(v, 0.f);
        C[(rowBase + r) * Nc + j] = v;
    }
}

__global__ void mlp3_kernel(const float* __restrict__ A, const float* __restrict__ W,
                            const float* __restrict__ b, float* __restrict__ C) {
    int g = blockIdx.x;
    int tid = threadIdx.x;
    float acc[4] = {0.f, 0.f, 0.f, 0.f};
    for (int k = tid; k < 1024; k += 256) {
        float a = A[g * 1024 + k];
        #pragma unroll
        for (int jj = 0; jj < 4; jj++) acc[jj] += a * W[k * 4 + jj];
    }
    #pragma unroll
    for (int jj = 0; jj < 4; jj++)
        #pragma unroll
        for (int off = 16; off; off >>= 1)
            acc[jj] += __shfl_xor_sync(0xffffffffu, acc[jj], off);
    __shared__ float red[8][4];
    int lane = tid & 31, wid = tid >> 5;
    if (lane == 0)
        #pragma unroll
        for (int jj = 0; jj < 4; jj++) red[wid][jj] = acc[jj];
    __syncthreads();
    if (tid < 4) {
        float s = b[tid];
        #pragma unroll
        for (int w = 0; w < 8; w++) s += red[w][tid];
        C[g * 4 + tid] = s;
    }
}

// ---------------- launch ----------------------------------------------------
extern "C" void kernel_launch(void* const* d_in, const int* in_sizes, int n_in,
                              void* d_out, int out_size) {
    const float* x      = (const float*)d_in[0];
    const int*   ei     = (const int*)  d_in[1];
    const float* W1     = (const float*)d_in[3];
    const float* a_src1 = (const float*)d_in[4];
    const float* a_dst1 = (const float*)d_in[5];
    const float* b1     = (const float*)d_in[6];
    const float* W2     = (const float*)d_in[7];
    const float* a_src2 = (const float*)d_in[8];
    const float* a_dst2 = (const float*)d_in[9];
    const float* b2     = (const float*)d_in[10];
    const float* Wl1    = (const float*)d_in[11];
    const float* bl1    = (const float*)d_in[12];
    const float* Wl2    = (const float*)d_in[13];
    const float* bl2    = (const float*)d_in[14];
    const float* Wl3    = (const float*)d_in[15];
    const float* bl3    = (const float*)d_in[16];
    float* out = (float*)d_out;
    (void)n_in; (void)in_sizes; (void)out_size;

    float *p_poolf, *p_z1, *p_z2;
    cudaGetSymbolAddress((void**)&p_poolf, g_poolf);
    cudaGetSymbolAddress((void**)&p_z1, g_z1);
    cudaGetSymbolAddress((void**)&p_z2, g_z2);

    // prep (counts is zero at module load and re-zeroed by offs_kernel)
    hist_kernel<<<(NET + 255) / 256, 256>>>(ei);
    bsum_kernel<<<NB, 256>>>();
    bscan_kernel<<<1, 256>>>();
    offs_kernel<<<NB, 256>>>();
    scatter_kernel<<<(NET + 255) / 256, 256>>>(ei);

    // layer 1
    gemm1_kernel<<<NN * 64 / 256, 256>>>(x, W1, a_src1, a_dst1);
    attnagg1_kernel<<<(NN + 7) / 8, 256>>>(b1);

    // layer 2
    gemm2_kernel<<<NN / 16, 256>>>(W2, a_src2, a_dst2);
    attnagg2_kernel<<<(NN + 7) / 8, 256>>>(b2);

    // pool + MLP
    pool_kernel<<<NG, 256>>>();
    dim3 grid1(512 / 256, NG / 16);
    mlp_tiled_kernel<<<grid1, 256>>>(p_poolf, Wl1, bl1, p_z1, 256, 512, 1);
    dim3 grid2(1024 / 256, NG / 16);
    mlp_tiled_kernel<<<grid2, 256>>>(p_z1, Wl2, bl2, p_z2, 512, 1024, 1);
    mlp3_kernel<<<NG, 256>>>(p_z2, Wl3, bl3, out);
}

// round 10
// speedup vs baseline: 1.2695x; 1.2695x over previous
#include <cuda_runtime.h>
#include <cuda_fp16.h>
#include <math.h>

#define NN 50000
#define NE 800000
#define NET (NE + NN)
#define NG 256
#define NB ((NN + 255) / 256)

// ---------------- device scratch ------------------------------------------
__device__ __half   g_h1[NN * 64];
__device__ float    g_ssrc1[NN * 4];
__device__ float    g_sdst1[NN * 4];
__device__ float    g_inv1[NN * 4];
__device__ float    g_out1[NN * 64];
__device__ __half   g_h2[NN * 256];
__device__ float    g_ssrc2[NN];
__device__ float    g_sdst2[NN];
__device__ float    g_inv2[NN];
__device__ __half   g_out2[NN * 256];
__device__ int      g_counts[NN];     // zero at load; re-zeroed by offs_kernel
__device__ int      g_blkdone;        // zero at load; reset by last block
__device__ int      g_offsets[NN + 1];
__device__ int      g_bsums[NB];
__device__ int      g_epos[NET];
__device__ int      g_csr_src[NET];
__device__ float    g_csr_w[NET * 4];
__device__ float    g_poolf[NG * 256];
__device__ float    g_z1[NG * 512];
__device__ float    g_z2[NG * 1024];

// ---------------- helpers --------------------------------------------------
__device__ __forceinline__ float leaky(float x) { return x > 0.f ? x : 0.2f * x; }
__device__ __forceinline__ float elu(float x)   { return x > 0.f ? x : expm1f(x); }

// ---------------- prep -----------------------------------------------------
// histogram + intra-bucket position (scatter then needs no atomics)
__global__ void hist_kernel(const int* __restrict__ ei) {
    int e = blockIdx.x * blockDim.x + threadIdx.x;
    if (e >= NET) return;
    int dst = (e < NE) ? ei[NE + e] : (e - NE);
    g_epos[e] = atomicAdd(&g_counts[dst], 1);
}

// block sums of counts + (last block) exclusive scan of the NB sums
__global__ void bsumscan_kernel() {
    __shared__ int ws[8];
    __shared__ int islast_s;
    int tid = threadIdx.x, lane = tid & 31, wid = tid >> 5;
    int i = blockIdx.x * 256 + tid;
    int v = (i < NN) ? g_counts[i] : 0;
    int r = v;
    #pragma unroll
    for (int off = 16; off; off >>= 1) r += __shfl_xor_sync(0xffffffffu, r, off);
    if (lane == 0) ws[wid] = r;
    __syncthreads();
    if (tid == 0) {
        int s = 0;
        #pragma unroll
        for (int w = 0; w < 8; w++) s += ws[w];
        g_bsums[blockIdx.x] = s;
        __threadfence();
        int pos = atomicAdd(&g_blkdone, 1);
        islast_s = (pos == gridDim.x - 1);
    }
    __syncthreads();
    if (!islast_s) return;
    // last block: exclusive scan of g_bsums[0..NB)
    __shared__ int wsum[8];
    int bv = (tid < NB) ? g_bsums[tid] : 0;
    int s = bv;
    #pragma unroll
    for (int off = 1; off < 32; off <<= 1) {
        int u = __shfl_up_sync(0xffffffffu, s, off);
        if (lane >= off) s += u;
    }
    if (lane == 31) wsum[wid] = s;
    __syncthreads();
    if (wid == 0 && lane < 8) {
        int t2 = wsum[lane];
        #pragma unroll
        for (int off = 1; off < 8; off <<= 1) {
            int u = __shfl_up_sync(0xffu, t2, off);
            if (lane >= off) t2 += u;
        }
        wsum[lane] = t2;
    }
    __syncthreads();
    int pre = (wid > 0) ? wsum[wid - 1] : 0;
    if (tid < NB) g_bsums[tid] = pre + s - bv;
    if (tid == 0) g_blkdone = 0;   // restore replay invariant
}

// offsets from counts + block bases; zeroes counts (replay invariant)
__global__ void offs_kernel() {
    __shared__ int wsum[8];
    int t = threadIdx.x, lane = t & 31, wid = t >> 5;
    int i = blockIdx.x * 256 + t;
    int v = (i < NN) ? g_counts[i] : 0;
    int s = v;
    #pragma unroll
    for (int off = 1; off < 32; off <<= 1) {
        int u = __shfl_up_sync(0xffffffffu, s, off);
        if (lane >= off) s += u;
    }
    if (lane == 31) wsum[wid] = s;
    __syncthreads();
    if (wid == 0 && lane < 8) {
        int ws = wsum[lane];
        #pragma unroll
        for (int off = 1; off < 8; off <<= 1) {
            int u = __shfl_up_sync(0xffu, ws, off);
            if (lane >= off) ws += u;
        }
        wsum[lane] = ws;
    }
    __syncthreads();
    int pre = (wid > 0) ? wsum[wid - 1] : 0;
    if (i < NN) {
        g_offsets[i] = g_bsums[blockIdx.x] + pre + s - v;
        g_counts[i] = 0;
    }
    if (i == 0) g_offsets[NN] = NET;
}

__global__ void scatter_kernel(const int* __restrict__ ei) {
    int e = blockIdx.x * blockDim.x + threadIdx.x;
    if (e >= NET) return;
    int src, dst;
    if (e < NE) { src = ei[e]; dst = ei[NE + e]; }
    else        { src = dst = e - NE; }
    g_csr_src[g_offsets[dst] + g_epos[e]] = src;
}

// ---------------- GAT layer 1 ----------------------------------------------
// h1 = x @ W1 (fp16 store), fused s1 (16-lane butterfly per head)
__global__ void gemm1_kernel(const float* __restrict__ x, const float* __restrict__ W1,
                             const float* __restrict__ a_src, const float* __restrict__ a_dst) {
    int idx = blockIdx.x * blockDim.x + threadIdx.x;   // NN*64 exact
    int n = idx >> 6, j = idx & 63;
    const float* xr = x + n * 27;
    float acc = 0.f;
    #pragma unroll
    for (int k = 0; k < 27; k++) acc += xr[k] * W1[k * 64 + j];
    g_h1[idx] = __float2half_rn(acc);
    float ps = acc * a_src[j];
    float pd = acc * a_dst[j];
    #pragma unroll
    for (int off = 8; off; off >>= 1) {
        ps += __shfl_xor_sync(0xffffffffu, ps, off);
        pd += __shfl_xor_sync(0xffffffffu, pd, off);
    }
    if ((j & 15) == 0) {
        int h = j >> 4;
        g_ssrc1[n * 4 + h] = ps;
        g_sdst1[n * 4 + h] = pd;
    }
}

// single-pass attention (no max subtraction — scores are O(10), exp safe):
// warp per node; gather leaky scores, exp, store to csr_w, sum den; inv/node.
template <int H>
__global__ void attn_kernel(const float* __restrict__ ssrc, const float* __restrict__ sdst,
                            float* __restrict__ csr_w, float* __restrict__ ginv) {
    int node = blockIdx.x * 8 + (threadIdx.x >> 5);
    if (node >= NN) return;
    int lane = threadIdx.x & 31;
    int beg = g_offsets[node], end = g_offsets[node + 1];
    float sd[H], den[H];
    #pragma unroll
    for (int h = 0; h < H; h++) { sd[h] = sdst[node * H + h]; den[h] = 0.f; }

    for (int i = beg + lane; i < end; i += 32) {
        int s = g_csr_src[i];
        if (H == 4) {
            float4 sv = *(const float4*)(ssrc + s * 4);
            float4 e;
            e.x = __expf(leaky(sv.x + sd[0]));
            e.y = __expf(leaky(sv.y + sd[1]));
            e.z = __expf(leaky(sv.z + sd[2]));
            e.w = __expf(leaky(sv.w + sd[3]));
            *(float4*)(csr_w + i * 4) = e;
            den[0] += e.x; den[1] += e.y; den[2] += e.z; den[3] += e.w;
        } else {
            float e = __expf(leaky(ssrc[s] + sd[0]));
            csr_w[i] = e;
            den[0] += e;
        }
    }
    #pragma unroll
    for (int h = 0; h < H; h++)
        #pragma unroll
        for (int off = 16; off; off >>= 1)
            den[h] += __shfl_xor_sync(0xffffffffu, den[h], off);
    if (lane == 0)
        #pragma unroll
        for (int h = 0; h < H; h++)
            ginv[node * H + h] = 1.f / (den[h] + 1e-16f);
}

// agg1: 16 threads/node (4 fp16 ch each via uint2), 16 nodes/block
__global__ void agg1_kernel(const float* __restrict__ b1) {
    int node = blockIdx.x * 16 + (threadIdx.x >> 4);
    int t = threadIdx.x & 15;        // ch = 4t .. 4t+3
    int h = t >> 2;                  // head
    float acc0 = 0.f, acc1 = 0.f, acc2 = 0.f, acc3 = 0.f;
    int beg = g_offsets[node], end = g_offsets[node + 1];
    const __half* h1 = g_h1;
    for (int i = beg; i < end; i++) {
        int s = g_csr_src[i];
        float w = g_csr_w[i * 4 + h];
        uint2 raw = *(const uint2*)(h1 + s * 64 + t * 4);
        float2 v0 = __half22float2(*(const __half2*)&raw.x);
        float2 v1 = __half22float2(*(const __half2*)&raw.y);
        acc0 += w * v0.x; acc1 += w * v0.y; acc2 += w * v1.x; acc3 += w * v1.y;
    }
    float inv = g_inv1[node * 4 + h];
    float4 bb = *(const float4*)(b1 + t * 4);
    float4 o;
    o.x = elu(acc0 * inv + bb.x);
    o.y = elu(acc1 * inv + bb.y);
    o.z = elu(acc2 * inv + bb.z);
    o.w = elu(acc3 * inv + bb.w);
    *(float4*)(g_out1 + node * 64 + t * 4) = o;
}

// ---------------- GAT layer 2 ----------------------------------------------
// h2 = out1 @ W2 -> fp16; s2 fused. 16 rows / 256-thread block.
__global__ void gemm2_kernel(const float* __restrict__ W2,
                             const float* __restrict__ a_src, const float* __restrict__ a_dst) {
    __shared__ float sA[16][64];
    __shared__ float sred[8][16][2];
    int nodeBase = blockIdx.x * 16;          // 3125 blocks, exact
    int tid = threadIdx.x;
    for (int t = tid; t < 16 * 64; t += 256) {
        int r = t >> 6, c = t & 63;
        sA[r][c] = g_out1[(nodeBase + r) * 64 + c];
    }
    __syncthreads();
    float acc[16];
    #pragma unroll
    for (int r = 0; r < 16; r++) acc[r] = 0.f;
    int j = tid;
    #pragma unroll 4
    for (int k = 0; k < 64; k++) {
        float w = W2[k * 256 + j];
        #pragma unroll
        for (int r = 0; r < 16; r++) acc[r] += sA[r][k] * w;
    }
    float aj_s = a_src[j], aj_d = a_dst[j];
    int lane = tid & 31, wid = tid >> 5;
    #pragma unroll
    for (int r = 0; r < 16; r++) {
        g_h2[(nodeBase + r) * 256 + j] = __float2half_rn(acc[r]);
        float ps = acc[r] * aj_s, pd = acc[r] * aj_d;
        #pragma unroll
        for (int off = 16; off; off >>= 1) {
            ps += __shfl_xor_sync(0xffffffffu, ps, off);
            pd += __shfl_xor_sync(0xffffffffu, pd, off);
        }
        if (lane == 0) { sred[wid][r][0] = ps; sred[wid][r][1] = pd; }
    }
    __syncthreads();
    if (tid < 32) {
        int r = tid >> 1, which = tid & 1;
        float s = 0.f;
        #pragma unroll
        for (int w = 0; w < 8; w++) s += sred[w][r][which];
        if (which == 0) g_ssrc2[nodeBase + r] = s;
        else            g_sdst2[nodeBase + r] = s;
    }
}

// agg2: 32 threads/node (8 fp16 ch each via uint4), 8 nodes/block; fp16 out
__global__ void agg2_kernel(const float* __restrict__ b2) {
    int node = blockIdx.x * 8 + (threadIdx.x >> 5);
    int t = threadIdx.x & 31;        // ch = 8t .. 8t+7
    float acc[8];
    #pragma unroll
    for (int c = 0; c < 8; c++) acc[c] = 0.f;
    int beg = g_offsets[node], end = g_offsets[node + 1];
    const __half* h2 = g_h2;
    for (int i = beg; i < end; i++) {
        int s = g_csr_src[i];
        float w = g_csr_w[i];
        uint4 raw = *(const uint4*)(h2 + s * 256 + t * 8);
        const __half2* hp = (const __half2*)&raw;
        #pragma unroll
        for (int c = 0; c < 4; c++) {
            float2 v = __half22float2(hp[c]);
            acc[2 * c]     += w * v.x;
            acc[2 * c + 1] += w * v.y;
        }
    }
    float inv = g_inv2[node];
    __half2 ov[4];
    #pragma unroll
    for (int c = 0; c < 4; c++) {
        float2 o;
        o.x = elu(acc[2 * c]     * inv + b2[t * 8 + 2 * c]);
        o.y = elu(acc[2 * c + 1] * inv + b2[t * 8 + 2 * c + 1]);
        ov[c] = __float22half2_rn(o);
    }
    *(uint4*)(g_out2 + node * 256 + t * 8) = *(const uint4*)ov;
}

// ---------------- pool + MLP ------------------------------------------------
__global__ void pool_kernel() {
    int g = blockIdx.x;
    int j = threadIdx.x;
    int start = (g * NN + NG - 1) / NG;
    int end   = ((g + 1) * NN + NG - 1) / NG;
    float mx = -3.4e38f;
    for (int n = start; n < end; n++)
        mx = fmaxf(mx, __half2float(g_out2[n * 256 + j]));
    g_poolf[g * 256 + j] = mx;
}

__global__ void mlp_tiled_kernel(const float* __restrict__ A, const float* __restrict__ W,
                                 const float* __restrict__ b, float* __restrict__ C,
                                 int K, int Nc, int do_relu) {
    __shared__ float sA[16][64];
    int rowBase = blockIdx.y * 16;
    int j = blockIdx.x * 256 + threadIdx.x;
    float acc[16];
    #pragma unroll
    for (int r = 0; r < 16; r++) acc[r] = 0.f;
    for (int k0 = 0; k0 < K; k0 += 64) {
        for (int t = threadIdx.x; t < 16 * 64; t += 256) {
            int r = t >> 6, c = t & 63;
            sA[r][c] = A[(rowBase + r) * K + k0 + c];
        }
        __syncthreads();
        #pragma unroll 4
        for (int kk = 0; kk < 64; kk++) {
            float w = W[(k0 + kk) * Nc + j];
            #pragma unroll
            for (int r = 0; r < 16; r++) acc[r] += sA[r][kk] * w;
        }
        __syncthreads();
    }
    float bj = b[j];
    #pragma unroll
    for (int r = 0; r < 16; r++) {
        float v = acc[r] + bj;
        if (do_relu) v = fmaxf(v, 0.f);
        C[(rowBase + r) * Nc + j] = v;
    }
}

__global__ void mlp3_kernel(const float* __restrict__ A, const float* __restrict__ W,
                            const float* __restrict__ b, float* __restrict__ C) {
    int g = blockIdx.x;
    int tid = threadIdx.x;
    float acc[4] = {0.f, 0.f, 0.f, 0.f};
    for (int k = tid; k < 1024; k += 256) {
        float a = A[g * 1024 + k];
        #pragma unroll
        for (int jj = 0; jj < 4; jj++) acc[jj] += a * W[k * 4 + jj];
    }
    #pragma unroll
    for (int jj = 0; jj < 4; jj++)
        #pragma unroll
        for (int off = 16; off; off >>= 1)
            acc[jj] += __shfl_xor_sync(0xffffffffu, acc[jj], off);
    __shared__ float red[8][4];
    int lane = tid & 31, wid = tid >> 5;
    if (lane == 0)
        #pragma unroll
        for (int jj = 0; jj < 4; jj++) red[wid][jj] = acc[jj];
    __syncthreads();
    if (tid < 4) {
        float s = b[tid];
        #pragma unroll
        for (int w = 0; w < 8; w++) s += red[w][tid];
        C[g * 4 + tid] = s;
    }
}

// ---------------- launch ----------------------------------------------------
extern "C" void kernel_launch(void* const* d_in, const int* in_sizes, int n_in,
                              void* d_out, int out_size) {
    const float* x      = (const float*)d_in[0];
    const int*   ei     = (const int*)  d_in[1];
    const float* W1     = (const float*)d_in[3];
    const float* a_src1 = (const float*)d_in[4];
    const float* a_dst1 = (const float*)d_in[5];
    const float* b1     = (const float*)d_in[6];
    const float* W2     = (const float*)d_in[7];
    const float* a_src2 = (const float*)d_in[8];
    const float* a_dst2 = (const float*)d_in[9];
    const float* b2     = (const float*)d_in[10];
    const float* Wl1    = (const float*)d_in[11];
    const float* bl1    = (const float*)d_in[12];
    const float* Wl2    = (const float*)d_in[13];
    const float* bl2    = (const float*)d_in[14];
    const float* Wl3    = (const float*)d_in[15];
    const float* bl3    = (const float*)d_in[16];
    float* out = (float*)d_out;
    (void)n_in; (void)in_sizes; (void)out_size;

    float *p_ssrc1, *p_sdst1, *p_inv1, *p_ssrc2, *p_sdst2, *p_inv2,
          *p_csr_w, *p_poolf, *p_z1, *p_z2;
    cudaGetSymbolAddress((void**)&p_ssrc1, g_ssrc1);
    cudaGetSymbolAddress((void**)&p_sdst1, g_sdst1);
    cudaGetSymbolAddress((void**)&p_inv1, g_inv1);
    cudaGetSymbolAddress((void**)&p_ssrc2, g_ssrc2);
    cudaGetSymbolAddress((void**)&p_sdst2, g_sdst2);
    cudaGetSymbolAddress((void**)&p_inv2, g_inv2);
    cudaGetSymbolAddress((void**)&p_csr_w, g_csr_w);
    cudaGetSymbolAddress((void**)&p_poolf, g_poolf);
    cudaGetSymbolAddress((void**)&p_z1, g_z1);
    cudaGetSymbolAddress((void**)&p_z2, g_z2);

    // prep (gemm1 is independent of prep — placed 4th so ncu profiles it)
    hist_kernel<<<(NET + 255) / 256, 256>>>(ei);
    bsumscan_kernel<<<NB, 256>>>();
    offs_kernel<<<NB, 256>>>();
    gemm1_kernel<<<NN * 64 / 256, 256>>>(x, W1, a_src1, a_dst1);
    scatter_kernel<<<(NET + 255) / 256, 256>>>(ei);

    // layer 1
    attn_kernel<4><<<(NN + 7) / 8, 256>>>(p_ssrc1, p_sdst1, p_csr_w, p_inv1);
    agg1_kernel<<<NN / 16, 256>>>(b1);

    // layer 2
    gemm2_kernel<<<NN / 16, 256>>>(W2, a_src2, a_dst2);
    attn_kernel<1><<<(NN + 7) / 8, 256>>>(p_ssrc2, p_sdst2, p_csr_w, p_inv2);
    agg2_kernel<<<NN / 8, 256>>>(b2);

    // pool + MLP
    pool_kernel<<<NG, 256>>>();
    dim3 grid1(512 / 256, NG / 16);
    mlp_tiled_kernel<<<grid1, 256>>>(p_poolf, Wl1, bl1, p_z1, 256, 512, 1);
    dim3 grid2(1024 / 256, NG / 16);
    mlp_tiled_kernel<<<grid2, 256>>>(p_z1, Wl2, bl2, p_z2, 512, 1024, 1);
    mlp3_kernel<<<NG, 256>>>(p_z2, Wl3, bl3, out);
}

// round 11
// speedup vs baseline: 1.3700x; 1.0792x over previous
#include <cuda_runtime.h>
#include <cuda_fp16.h>
#include <math.h>

#define NN 50000
#define NE 800000
#define NET (NE + NN)
#define NG 256
#define NB ((NN + 255) / 256)

// ---------------- device scratch ------------------------------------------
__device__ __half   g_h1[NN * 64];
__device__ float    g_ssrc1[NN * 4];
__device__ float    g_sdst1[NN * 4];
__device__ float    g_inv1[NN * 4];
__device__ float    g_out1[NN * 64];
__device__ __half   g_h2[NN * 256];
__device__ float    g_ssrc2[NN];
__device__ float    g_sdst2[NN];
__device__ float    g_inv2[NN];
__device__ __half   g_out2[NN * 256];
__device__ int      g_counts[NN];     // zero at load; re-zeroed by offs_kernel
__device__ int      g_blkdone;        // zero at load; reset by last block
__device__ int      g_offsets[NN + 1];
__device__ int      g_bsums[NB];
__device__ int      g_epos[NET];
__device__ int      g_csr_src[NET];
__device__ float    g_csr_w[NET * 4];
__device__ float    g_poolf[NG * 256];
__device__ float    g_z1[NG * 512];
__device__ float    g_z2[NG * 1024];

// ---------------- helpers --------------------------------------------------
__device__ __forceinline__ float leaky(float x) { return x > 0.f ? x : 0.2f * x; }
__device__ __forceinline__ float elu(float x)   { return x > 0.f ? x : expm1f(x); }

// ---------------- prep -----------------------------------------------------
__global__ void hist_kernel(const int* __restrict__ ei) {
    int e = blockIdx.x * blockDim.x + threadIdx.x;
    if (e >= NET) return;
    int dst = (e < NE) ? ei[NE + e] : (e - NE);
    g_epos[e] = atomicAdd(&g_counts[dst], 1);
}

// block sums of counts + (last block) exclusive scan of the NB sums
__global__ void bsumscan_kernel() {
    __shared__ int ws[8];
    __shared__ int islast_s;
    int tid = threadIdx.x, lane = tid & 31, wid = tid >> 5;
    int i = blockIdx.x * 256 + tid;
    int v = (i < NN) ? g_counts[i] : 0;
    int r = v;
    #pragma unroll
    for (int off = 16; off; off >>= 1) r += __shfl_xor_sync(0xffffffffu, r, off);
    if (lane == 0) ws[wid] = r;
    __syncthreads();
    if (tid == 0) {
        int s = 0;
        #pragma unroll
        for (int w = 0; w < 8; w++) s += ws[w];
        g_bsums[blockIdx.x] = s;
        __threadfence();
        int pos = atomicAdd(&g_blkdone, 1);
        islast_s = (pos == gridDim.x - 1);
    }
    __syncthreads();
    if (!islast_s) return;
    __shared__ int wsum[8];
    int bv = (tid < NB) ? g_bsums[tid] : 0;
    int s = bv;
    #pragma unroll
    for (int off = 1; off < 32; off <<= 1) {
        int u = __shfl_up_sync(0xffffffffu, s, off);
        if (lane >= off) s += u;
    }
    if (lane == 31) wsum[wid] = s;
    __syncthreads();
    if (wid == 0 && lane < 8) {
        int t2 = wsum[lane];
        #pragma unroll
        for (int off = 1; off < 8; off <<= 1) {
            int u = __shfl_up_sync(0xffu, t2, off);
            if (lane >= off) t2 += u;
        }
        wsum[lane] = t2;
    }
    __syncthreads();
    int pre = (wid > 0) ? wsum[wid - 1] : 0;
    if (tid < NB) g_bsums[tid] = pre + s - bv;
    if (tid == 0) g_blkdone = 0;
}

// offsets from counts + block bases; zeroes counts (replay invariant)
__global__ void offs_kernel() {
    __shared__ int wsum[8];
    int t = threadIdx.x, lane = t & 31, wid = t >> 5;
    int i = blockIdx.x * 256 + t;
    int v = (i < NN) ? g_counts[i] : 0;
    int s = v;
    #pragma unroll
    for (int off = 1; off < 32; off <<= 1) {
        int u = __shfl_up_sync(0xffffffffu, s, off);
        if (lane >= off) s += u;
    }
    if (lane == 31) wsum[wid] = s;
    __syncthreads();
    if (wid == 0 && lane < 8) {
        int ws = wsum[lane];
        #pragma unroll
        for (int off = 1; off < 8; off <<= 1) {
            int u = __shfl_up_sync(0xffu, ws, off);
            if (lane >= off) ws += u;
        }
        wsum[lane] = ws;
    }
    __syncthreads();
    int pre = (wid > 0) ? wsum[wid - 1] : 0;
    if (i < NN) {
        g_offsets[i] = g_bsums[blockIdx.x] + pre + s - v;
        g_counts[i] = 0;
    }
    if (i == 0) g_offsets[NN] = NET;
}

__global__ void scatter_kernel(const int* __restrict__ ei) {
    int e = blockIdx.x * blockDim.x + threadIdx.x;
    if (e >= NET) return;
    int src, dst;
    if (e < NE) { src = ei[e]; dst = ei[NE + e]; }
    else        { src = dst = e - NE; }
    g_csr_src[g_offsets[dst] + g_epos[e]] = src;
}

// ---------------- GAT layer 1 ----------------------------------------------
// h1 = x @ W1 (fp16), register-tiled: thread computes 4 consecutive j for one
// node (float4 W1, scalar x, uint2 h1 store). Fused s1 via 4-lane butterfly.
__global__ void gemm1_kernel(const float* __restrict__ x, const float* __restrict__ W1,
                             const float* __restrict__ a_src, const float* __restrict__ a_dst) {
    int tid = threadIdx.x;
    int jt = tid & 15, nsub = tid >> 4;     // 16 nodes/block, j-group of 4
    int n = blockIdx.x * 16 + nsub;         // NN/16 = 3125 blocks, exact
    int j0 = jt * 4;
    const float* xr = x + n * 27;
    float4 acc = make_float4(0.f, 0.f, 0.f, 0.f);
    #pragma unroll
    for (int k = 0; k < 27; k++) {
        float xk = xr[k];
        float4 w = *(const float4*)(W1 + k * 64 + j0);
        acc.x += xk * w.x; acc.y += xk * w.y; acc.z += xk * w.z; acc.w += xk * w.w;
    }
    __half2 hv[2];
    hv[0] = __floats2half2_rn(acc.x, acc.y);
    hv[1] = __floats2half2_rn(acc.z, acc.w);
    *(uint2*)(g_h1 + n * 64 + j0) = *(const uint2*)hv;
    float4 as = *(const float4*)(a_src + j0);
    float4 ad = *(const float4*)(a_dst + j0);
    float ps = acc.x * as.x + acc.y * as.y + acc.z * as.z + acc.w * as.w;
    float pd = acc.x * ad.x + acc.y * ad.y + acc.z * ad.z + acc.w * ad.w;
    // reduce over the 4 lanes of this head (jt & 3)
    ps += __shfl_xor_sync(0xffffffffu, ps, 1);
    ps += __shfl_xor_sync(0xffffffffu, ps, 2);
    pd += __shfl_xor_sync(0xffffffffu, pd, 1);
    pd += __shfl_xor_sync(0xffffffffu, pd, 2);
    if ((jt & 3) == 0) {
        int h = jt >> 2;
        g_ssrc1[n * 4 + h] = ps;
        g_sdst1[n * 4 + h] = pd;
    }
}

// single-pass attention (no max subtraction — scores are O(10), exp safe)
template <int H>
__global__ void attn_kernel(const float* __restrict__ ssrc, const float* __restrict__ sdst,
                            float* __restrict__ csr_w, float* __restrict__ ginv) {
    int node = blockIdx.x * 8 + (threadIdx.x >> 5);
    if (node >= NN) return;
    int lane = threadIdx.x & 31;
    int beg = g_offsets[node], end = g_offsets[node + 1];
    float sd[H], den[H];
    #pragma unroll
    for (int h = 0; h < H; h++) { sd[h] = sdst[node * H + h]; den[h] = 0.f; }

    for (int i = beg + lane; i < end; i += 32) {
        int s = g_csr_src[i];
        if (H == 4) {
            float4 sv = *(const float4*)(ssrc + s * 4);
            float4 e;
            e.x = __expf(leaky(sv.x + sd[0]));
            e.y = __expf(leaky(sv.y + sd[1]));
            e.z = __expf(leaky(sv.z + sd[2]));
            e.w = __expf(leaky(sv.w + sd[3]));
            *(float4*)(csr_w + i * 4) = e;
            den[0] += e.x; den[1] += e.y; den[2] += e.z; den[3] += e.w;
        } else {
            float e = __expf(leaky(ssrc[s] + sd[0]));
            csr_w[i] = e;
            den[0] += e;
        }
    }
    #pragma unroll
    for (int h = 0; h < H; h++)
        #pragma unroll
        for (int off = 16; off; off >>= 1)
            den[h] += __shfl_xor_sync(0xffffffffu, den[h], off);
    if (lane == 0)
        #pragma unroll
        for (int h = 0; h < H; h++)
            ginv[node * H + h] = 1.f / (den[h] + 1e-16f);
}

// agg1: 16 threads/node (4 fp16 ch each via uint2), 16 nodes/block
__global__ void agg1_kernel(const float* __restrict__ b1) {
    int node = blockIdx.x * 16 + (threadIdx.x >> 4);
    int t = threadIdx.x & 15;        // ch = 4t .. 4t+3
    int h = t >> 2;                  // head
    float acc0 = 0.f, acc1 = 0.f, acc2 = 0.f, acc3 = 0.f;
    int beg = g_offsets[node], end = g_offsets[node + 1];
    const __half* h1 = g_h1;
    for (int i = beg; i < end; i++) {
        int s = g_csr_src[i];
        float w = g_csr_w[i * 4 + h];
        uint2 raw = *(const uint2*)(h1 + s * 64 + t * 4);
        float2 v0 = __half22float2(*(const __half2*)&raw.x);
        float2 v1 = __half22float2(*(const __half2*)&raw.y);
        acc0 += w * v0.x; acc1 += w * v0.y; acc2 += w * v1.x; acc3 += w * v1.y;
    }
    float inv = g_inv1[node * 4 + h];
    float4 bb = *(const float4*)(b1 + t * 4);
    float4 o;
    o.x = elu(acc0 * inv + bb.x);
    o.y = elu(acc1 * inv + bb.y);
    o.z = elu(acc2 * inv + bb.z);
    o.w = elu(acc3 * inv + bb.w);
    *(float4*)(g_out1 + node * 64 + t * 4) = o;
}

// ---------------- GAT layer 2 ----------------------------------------------
// h2 = out1 @ W2 -> fp16; s2 fused. 16 rows / 256-thread block.
__global__ void gemm2_kernel(const float* __restrict__ W2,
                             const float* __restrict__ a_src, const float* __restrict__ a_dst) {
    __shared__ float sA[16][64];
    __shared__ float sred[8][16][2];
    int nodeBase = blockIdx.x * 16;          // 3125 blocks, exact
    int tid = threadIdx.x;
    for (int t = tid; t < 16 * 64; t += 256) {
        int r = t >> 6, c = t & 63;
        sA[r][c] = g_out1[(nodeBase + r) * 64 + c];
    }
    __syncthreads();
    float acc[16];
    #pragma unroll
    for (int r = 0; r < 16; r++) acc[r] = 0.f;
    int j = tid;
    #pragma unroll 4
    for (int k = 0; k < 64; k++) {
        float w = W2[k * 256 + j];
        #pragma unroll
        for (int r = 0; r < 16; r++) acc[r] += sA[r][k] * w;
    }
    float aj_s = a_src[j], aj_d = a_dst[j];
    int lane = tid & 31, wid = tid >> 5;
    #pragma unroll
    for (int r = 0; r < 16; r++) {
        g_h2[(nodeBase + r) * 256 + j] = __float2half_rn(acc[r]);
        float ps = acc[r] * aj_s, pd = acc[r] * aj_d;
        #pragma unroll
        for (int off = 16; off; off >>= 1) {
            ps += __shfl_xor_sync(0xffffffffu, ps, off);
            pd += __shfl_xor_sync(0xffffffffu, pd, off);
        }
        if (lane == 0) { sred[wid][r][0] = ps; sred[wid][r][1] = pd; }
    }
    __syncthreads();
    if (tid < 32) {
        int r = tid >> 1, which = tid & 1;
        float s = 0.f;
        #pragma unroll
        for (int w = 0; w < 8; w++) s += sred[w][r][which];
        if (which == 0) g_ssrc2[nodeBase + r] = s;
        else            g_sdst2[nodeBase + r] = s;
    }
}

// agg2: 32 threads/node (8 fp16 ch each via uint4), 8 nodes/block; fp16 out
__global__ void agg2_kernel(const float* __restrict__ b2) {
    int node = blockIdx.x * 8 + (threadIdx.x >> 5);
    int t = threadIdx.x & 31;        // ch = 8t .. 8t+7
    float acc[8];
    #pragma unroll
    for (int c = 0; c < 8; c++) acc[c] = 0.f;
    int beg = g_offsets[node], end = g_offsets[node + 1];
    const __half* h2 = g_h2;
    for (int i = beg; i < end; i++) {
        int s = g_csr_src[i];
        float w = g_csr_w[i];
        uint4 raw = *(const uint4*)(h2 + s * 256 + t * 8);
        const __half2* hp = (const __half2*)&raw;
        #pragma unroll
        for (int c = 0; c < 4; c++) {
            float2 v = __half22float2(hp[c]);
            acc[2 * c]     += w * v.x;
            acc[2 * c + 1] += w * v.y;
        }
    }
    float inv = g_inv2[node];
    __half2 ov[4];
    #pragma unroll
    for (int c = 0; c < 4; c++) {
        float2 o;
        o.x = elu(acc[2 * c]     * inv + b2[t * 8 + 2 * c]);
        o.y = elu(acc[2 * c + 1] * inv + b2[t * 8 + 2 * c + 1]);
        ov[c] = __float22half2_rn(o);
    }
    *(uint4*)(g_out2 + node * 256 + t * 8) = *(const uint4*)ov;
}

// ---------------- pool + MLP ------------------------------------------------
__global__ void pool_kernel() {
    int g = blockIdx.x;
    int j = threadIdx.x;
    int start = (g * NN + NG - 1) / NG;
    int end   = ((g + 1) * NN + NG - 1) / NG;
    float mx = -3.4e38f;
    for (int n = start; n < end; n++)
        mx = fmaxf(mx, __half2float(g_out2[n * 256 + j]));
    g_poolf[g * 256 + j] = mx;
}

// tiled MLP: 8 rows x 256 cols per block (2x blocks vs 16-row version)
__global__ void mlp_tiled_kernel(const float* __restrict__ A, const float* __restrict__ W,
                                 const float* __restrict__ b, float* __restrict__ C,
                                 int K, int Nc, int do_relu) {
    __shared__ float sA[8][64];
    int rowBase = blockIdx.y * 8;
    int j = blockIdx.x * 256 + threadIdx.x;
    float acc[8];
    #pragma unroll
    for (int r = 0; r < 8; r++) acc[r] = 0.f;
    for (int k0 = 0; k0 < K; k0 += 64) {
        for (int t = threadIdx.x; t < 8 * 64; t += 256) {
            int r = t >> 6, c = t & 63;
            sA[r][c] = A[(rowBase + r) * K + k0 + c];
        }
        __syncthreads();
        #pragma unroll 4
        for (int kk = 0; kk < 64; kk++) {
            float w = W[(k0 + kk) * Nc + j];
            #pragma unroll
            for (int r = 0; r < 8; r++) acc[r] += sA[r][kk] * w;
        }
        __syncthreads();
    }
    float bj = b[j];
    #pragma unroll
    for (int r = 0; r < 8; r++) {
        float v = acc[r] + bj;
        if (do_relu) v = fmaxf(v, 0.f);
        C[(rowBase + r) * Nc + j] = v;
    }
}

__global__ void mlp3_kernel(const float* __restrict__ A, const float* __restrict__ W,
                            const float* __restrict__ b, float* __restrict__ C) {
    int g = blockIdx.x;
    int tid = threadIdx.x;
    float acc[4] = {0.f, 0.f, 0.f, 0.f};
    for (int k = tid; k < 1024; k += 256) {
        float a = A[g * 1024 + k];
        #pragma unroll
        for (int jj = 0; jj < 4; jj++) acc[jj] += a * W[k * 4 + jj];
    }
    #pragma unroll
    for (int jj = 0; jj < 4; jj++)
        #pragma unroll
        for (int off = 16; off; off >>= 1)
            acc[jj] += __shfl_xor_sync(0xffffffffu, acc[jj], off);
    __shared__ float red[8][4];
    int lane = tid & 31, wid = tid >> 5;
    if (lane == 0)
        #pragma unroll
        for (int jj = 0; jj < 4; jj++) red[wid][jj] = acc[jj];
    __syncthreads();
    if (tid < 4) {
        float s = b[tid];
        #pragma unroll
        for (int w = 0; w < 8; w++) s += red[w][tid];
        C[g * 4 + tid] = s;
    }
}

// ---------------- launch ----------------------------------------------------
extern "C" void kernel_launch(void* const* d_in, const int* in_sizes, int n_in,
                              void* d_out, int out_size) {
    const float* x      = (const float*)d_in[0];
    const int*   ei     = (const int*)  d_in[1];
    const float* W1     = (const float*)d_in[3];
    const float* a_src1 = (const float*)d_in[4];
    const float* a_dst1 = (const float*)d_in[5];
    const float* b1     = (const float*)d_in[6];
    const float* W2     = (const float*)d_in[7];
    const float* a_src2 = (const float*)d_in[8];
    const float* a_dst2 = (const float*)d_in[9];
    const float* b2     = (const float*)d_in[10];
    const float* Wl1    = (const float*)d_in[11];
    const float* bl1    = (const float*)d_in[12];
    const float* Wl2    = (const float*)d_in[13];
    const float* bl2    = (const float*)d_in[14];
    const float* Wl3    = (const float*)d_in[15];
    const float* bl3    = (const float*)d_in[16];
    float* out = (float*)d_out;
    (void)n_in; (void)in_sizes; (void)out_size;

    float *p_ssrc1, *p_sdst1, *p_inv1, *p_ssrc2, *p_sdst2, *p_inv2,
          *p_csr_w, *p_poolf, *p_z1, *p_z2;
    cudaGetSymbolAddress((void**)&p_ssrc1, g_ssrc1);
    cudaGetSymbolAddress((void**)&p_sdst1, g_sdst1);
    cudaGetSymbolAddress((void**)&p_inv1, g_inv1);
    cudaGetSymbolAddress((void**)&p_ssrc2, g_ssrc2);
    cudaGetSymbolAddress((void**)&p_sdst2, g_sdst2);
    cudaGetSymbolAddress((void**)&p_inv2, g_inv2);
    cudaGetSymbolAddress((void**)&p_csr_w, g_csr_w);
    cudaGetSymbolAddress((void**)&p_poolf, g_poolf);
    cudaGetSymbolAddress((void**)&p_z1, g_z1);
    cudaGetSymbolAddress((void**)&p_z2, g_z2);

    // prep (gemm1 kept at launch #4 — that's the one ncu captures)
    hist_kernel<<<(NET + 255) / 256, 256>>>(ei);
    bsumscan_kernel<<<NB, 256>>>();
    offs_kernel<<<NB, 256>>>();
    gemm1_kernel<<<NN / 16, 256>>>(x, W1, a_src1, a_dst1);
    scatter_kernel<<<(NET + 255) / 256, 256>>>(ei);

    // layer 1
    attn_kernel<4><<<(NN + 7) / 8, 256>>>(p_ssrc1, p_sdst1, p_csr_w, p_inv1);
    agg1_kernel<<<NN / 16, 256>>>(b1);

    // layer 2
    gemm2_kernel<<<NN / 16, 256>>>(W2, a_src2, a_dst2);
    attn_kernel<1><<<(NN + 7) / 8, 256>>>(p_ssrc2, p_sdst2, p_csr_w, p_inv2);
    agg2_kernel<<<NN / 8, 256>>>(b2);

    // pool + MLP
    pool_kernel<<<NG, 256>>>();
    dim3 grid1(512 / 256, NG / 8);
    mlp_tiled_kernel<<<grid1, 256>>>(p_poolf, Wl1, bl1, p_z1, 256, 512, 1);
    dim3 grid2(1024 / 256, NG / 8);
    mlp_tiled_kernel<<<grid2, 256>>>(p_z1, Wl2, bl2, p_z2, 512, 1024, 1);
    mlp3_kernel<<<NG, 256>>>(p_z2, Wl3, bl3, out);
}